// round 9
// baseline (speedup 1.0000x reference)
#include <cuda_runtime.h>
#include <cuda_bf16.h>
#include <cstdint>

#define BB   4
#define NN   256
#define DIN  128
#define DE   64
#define NH   8
#define DK   16
#define HD   128
#define QR   8     // rows per qkv block

// ---------------------------------------------------------------------------
// device-global scratch (no allocations allowed)
// ---------------------------------------------------------------------------
__device__ float g_Q[BB * NN * HD];
__device__ float g_K[BB * NN * HD];   // pre-scaled by DK^-0.5
__device__ float g_V[BB * NN * HD];
__device__ __nv_bfloat16 g_Bhi[2 * HD * DE];  // [n=256][d=64]: n<128 -> WE2 col n, else WE col n-128
__device__ __nv_bfloat16 g_Blo[2 * HD * DE];

#define SMEM_SWZ(off) ((off) ^ (((off) >> 3) & 0x70))

__device__ __forceinline__ uint32_t smem_u32(const void* p) {
    uint32_t a;
    asm("{ .reg .u64 t; cvta.to.shared.u64 t, %1; cvt.u32.u64 %0, t; }" : "=r"(a) : "l"(p));
    return a;
}

// warp-level bf16 MMA (sm_80+, legal on plain sm_103 target)
__device__ __forceinline__ void mma16816(float* c, const uint32_t* a, const uint32_t* b) {
    asm volatile(
        "mma.sync.aligned.m16n8k16.row.col.f32.bf16.bf16.f32 "
        "{%0,%1,%2,%3}, {%4,%5,%6,%7}, {%8,%9}, {%0,%1,%2,%3};"
        : "+f"(c[0]), "+f"(c[1]), "+f"(c[2]), "+f"(c[3])
        : "r"(a[0]), "r"(a[1]), "r"(a[2]), "r"(a[3]), "r"(b[0]), "r"(b[1]));
}
__device__ __forceinline__ void ldmat_x4(uint32_t* r, uint32_t saddr) {
    asm volatile("ldmatrix.sync.aligned.m8n8.x4.shared.b16 {%0,%1,%2,%3}, [%4];"
        : "=r"(r[0]), "=r"(r[1]), "=r"(r[2]), "=r"(r[3]) : "r"(saddr));
}
// split a float2 into bf16x2 hi and bf16x2 lo words
__device__ __forceinline__ void split2(float2 v, uint32_t& hi, uint32_t& lo) {
    const __nv_bfloat16 hx = __float2bfloat16(v.x);
    const __nv_bfloat16 hy = __float2bfloat16(v.y);
    const __nv_bfloat16 lx = __float2bfloat16(v.x - __bfloat162float(hx));
    const __nv_bfloat16 ly = __float2bfloat16(v.y - __bfloat162float(hy));
    __nv_bfloat162 h2; h2.x = hx; h2.y = hy;
    __nv_bfloat162 l2; l2.x = lx; l2.y = ly;
    hi = *(uint32_t*)&h2;
    lo = *(uint32_t*)&l2;
}

// ---------------------------------------------------------------------------
// SMEM layout (dynamic). W persists at 0; staging region follows.
// ---------------------------------------------------------------------------
#define SM_B       0                       // Whi 32768, Wlo at +32768 -> [0, 65536)
#define SM_PE      65536                   // float2 staging: 64 cols * 257 * 8B = 131584
#define SM_QK      197120                  // 256*9*4 = 9216
#define SM_AM      206336                  // 256*4
#define SM_QROW    207360                  // 128*4
#define SM_REDD    207872                  // 256*4
#define SM_REDO    208896                  // 256*4
#define SMEM_TOTAL 209920

// ---------------------------------------------------------------------------
// Kernel 1: QKV projection, QR rows per block (amortize weight traffic).
// ---------------------------------------------------------------------------
__global__ __launch_bounds__(128) void qkv_kernel(
    const float* __restrict__ h,
    const float* __restrict__ WQ,
    const float* __restrict__ WK,
    const float* __restrict__ WV)
{
    __shared__ float sh[QR][DIN];
    const int rb = blockIdx.x * QR;
    const int t  = threadIdx.x;
    #pragma unroll
    for (int r = 0; r < QR; r++) sh[r][t] = h[(rb + r) * DIN + t];
    __syncthreads();

    float q[QR], k[QR], v[QR];
    #pragma unroll
    for (int r = 0; r < QR; r++) { q[r] = 0.f; k[r] = 0.f; v[r] = 0.f; }

    #pragma unroll 8
    for (int d4 = 0; d4 < DIN / 4; d4++) {
        float4 hv[QR];
        #pragma unroll
        for (int r = 0; r < QR; r++) hv[r] = *(const float4*)&sh[r][d4 * 4];
        #pragma unroll
        for (int c = 0; c < 4; c++) {
            const int d = d4 * 4 + c;
            const float wq = WQ[d * HD + t];
            const float wk = WK[d * HD + t];
            const float wv = WV[d * HD + t];
            #pragma unroll
            for (int r = 0; r < QR; r++) {
                const float hx = (&hv[r].x)[c];
                q[r] = fmaf(hx, wq, q[r]);
                k[r] = fmaf(hx, wk, k[r]);
                v[r] = fmaf(hx, wv, v[r]);
            }
        }
    }
    #pragma unroll
    for (int r = 0; r < QR; r++) {
        g_Q[(rb + r) * HD + t] = q[r];
        g_K[(rb + r) * HD + t] = k[r] * 0.25f;
        g_V[(rb + r) * HD + t] = v[r];
    }
}

// ---------------------------------------------------------------------------
// Kernel 2: weight split -> layout [n][d], bf16 hi/lo
// ---------------------------------------------------------------------------
__global__ __launch_bounds__(256) void conv_w_kernel(
    const float* __restrict__ WE, const float* __restrict__ WE2)
{
    const int idx = blockIdx.x * 256 + threadIdx.x;   // 0..16383
    const int n = idx >> 6, d = idx & 63;
    const float* W = (n < HD) ? WE2 : WE;
    const float w = W[d * HD + (n & (HD - 1))];
    const __nv_bfloat16 hi = __float2bfloat16(w);
    const __nv_bfloat16 lo = __float2bfloat16(w - __bfloat162float(hi));
    g_Bhi[idx] = hi;
    g_Blo[idx] = lo;
}

// ---------------------------------------------------------------------------
// Kernel 3: fused HMMA attention. One CTA per (b,i), 256 threads (8 warps).
//   S[256j x 256n] = [e_hi|e_lo|e_hi] @ [Whi;Whi;Wlo]^T  (3-term bf16 split)
//   A fragments loaded direct from gmem; B fragments via ldmatrix.x4.
// ---------------------------------------------------------------------------
__global__ __launch_bounds__(256, 1)
void attn_mma_kernel(
    const float* __restrict__ e,
    const float* __restrict__ mask,
    float* __restrict__ out)
{
    extern __shared__ char smem[];
    const uint32_t sbase = smem_u32(smem);
    const int t   = threadIdx.x;
    const int wid = t >> 5;
    const int lid = t & 31;
    const int gid = lid >> 2;        // 0..7
    const int tig = lid & 3;         // 0..3
    const int bi  = blockIdx.x;
    const int b   = bi >> 8;
    const int i   = bi & 255;

    float*  sQKv  = (float*)(smem + SM_QK);
    float*  sAmv  = (float*)(smem + SM_AM);
    float*  sQrow = (float*)(smem + SM_QROW);
    float2* sPE   = (float2*)(smem + SM_PE);
    float*  sRedD = (float*)(smem + SM_REDD);
    float*  sRedO = (float*)(smem + SM_REDO);

    // ---- load W (bf16 hi/lo) into SW128 smem: [256 rows x 128B] ----
    {
        const int ch = t & 7;          // 16B chunk within 128B row
        const int r0 = t >> 3;         // 32 rows per iteration
        #pragma unroll
        for (int it = 0; it < 8; it++) {
            const int row = it * 32 + r0;
            const uint32_t off = SMEM_SWZ(row * 128 + ch * 16);
            *(uint4*)(smem + SM_B + off)         = ((const uint4*)g_Bhi)[row * 8 + ch];
            *(uint4*)(smem + SM_B + 32768 + off) = ((const uint4*)g_Blo)[row * 8 + ch];
        }
    }

    // ---- A fragments direct from gmem: [mblk][kstep][hi/lo][4] ----
    uint32_t afr[2][4][2][4];
    {
        const float* __restrict__ eb = e + (size_t)bi * NN * DE;
        const int jb = wid * 32;
        #pragma unroll
        for (int mblk = 0; mblk < 2; mblk++) {
            const int r0 = jb + mblk * 16 + gid;
            #pragma unroll
            for (int ks = 0; ks < 4; ks++) {
                const int c0 = ks * 16 + tig * 2;
                const float2 v0 = *(const float2*)(eb + r0 * DE + c0);
                const float2 v1 = *(const float2*)(eb + (r0 + 8) * DE + c0);
                const float2 v2 = *(const float2*)(eb + r0 * DE + c0 + 8);
                const float2 v3 = *(const float2*)(eb + (r0 + 8) * DE + c0 + 8);
                split2(v0, afr[mblk][ks][0][0], afr[mblk][ks][1][0]);
                split2(v1, afr[mblk][ks][0][1], afr[mblk][ks][1][1]);
                split2(v2, afr[mblk][ks][0][2], afr[mblk][ks][1][2]);
                split2(v3, afr[mblk][ks][0][3], afr[mblk][ks][1][3]);
            }
        }
    }

    // ---- mask products + Q row ----
    sAmv[t] = mask[b * NN + i] * mask[b * NN + t];
    if (t < HD) sQrow[t] = g_Q[(size_t)bi * HD + t];
    __syncthreads();

    // ---- QK scores (fp32 exact): thread t owns j = t ----
    {
        const float4* __restrict__ Kp = (const float4*)(g_K + ((size_t)b * NN + t) * HD);
        #pragma unroll
        for (int hh = 0; hh < NH; hh++) {
            float s_ = 0.f;
            #pragma unroll
            for (int kk = 0; kk < DK / 4; kk++) {
                const float4 kv = Kp[hh * (DK / 4) + kk];
                const float* qp = &sQrow[hh * DK + kk * 4];
                s_ += kv.x * qp[0] + kv.y * qp[1] + kv.z * qp[2] + kv.w * qp[3];
            }
            sQKv[t * 9 + hh] = s_;
        }
    }
    // per-thread mask values for the 4 j rows this thread's frags cover
    __syncthreads();
    float am4[2][2];
    #pragma unroll
    for (int mblk = 0; mblk < 2; mblk++) {
        am4[mblk][0] = sAmv[wid * 32 + mblk * 16 + gid];
        am4[mblk][1] = sAmv[wid * 32 + mblk * 16 + gid + 8];
    }

    // ldmatrix lane roles: sel 0/1 -> score cols (k0-7 / k8-15), sel 2/3 -> E cols
    const int sel = lid >> 3;
    const int r8  = lid & 7;
    const int nsel = (sel >= 2) ? 128 : 0;        // E block offset
    const uint32_t koff16 = (sel & 1) * 16;

    // ---- main loop: two 64-col halves ----
    for (int h0 = 0; h0 < HD; h0 += 64) {
        // phase 1: HMMA scores + E, fragment epilogue -> staging
        #pragma unroll 1
        for (int cg = 0; cg < 8; cg++) {
            float accS[2][4] = {{0.f,0.f,0.f,0.f},{0.f,0.f,0.f,0.f}};
            float accE[2][4] = {{0.f,0.f,0.f,0.f},{0.f,0.f,0.f,0.f}};
            const int nrow = h0 + cg * 8 + r8 + nsel;     // ldmatrix source row
            const uint32_t rowbase = sbase + SM_B + (uint32_t)nrow * 128;
            const uint32_t xkey = ((uint32_t)nrow & 7) << 4;
            #pragma unroll
            for (int ks = 0; ks < 4; ks++) {
                // bmat = { bsh[0], bsh[1], beh[0], beh[1] } via one ldmatrix.x4
                const uint32_t addr = rowbase + (((uint32_t)ks * 32 + koff16) ^ xkey);
                uint32_t bh[4], bl[4];
                ldmat_x4(bh, addr);
                ldmat_x4(bl, addr + 32768);
                #pragma unroll
                for (int mblk = 0; mblk < 2; mblk++) {
                    mma16816(accS[mblk], afr[mblk][ks][0], bh + 0);  // Ahi*Whi
                    mma16816(accS[mblk], afr[mblk][ks][1], bh + 0);  // Alo*Whi
                    mma16816(accS[mblk], afr[mblk][ks][0], bl + 0);  // Ahi*Wlo
                    mma16816(accE[mblk], afr[mblk][ks][0], bh + 2);
                    mma16816(accE[mblk], afr[mblk][ks][1], bh + 2);
                    mma16816(accE[mblk], afr[mblk][ks][0], bl + 2);
                }
            }
            // fragment epilogue: clip/exp/mask -> packed staging
            #pragma unroll
            for (int mblk = 0; mblk < 2; mblk++) {
                #pragma unroll
                for (int u = 0; u < 4; u++) {
                    const int j  = wid * 32 + mblk * 16 + gid + (u >> 1) * 8;
                    const int cn = cg * 8 + tig * 2 + (u & 1);
                    const int head = (h0 + cn) >> 4;
                    float s = sQKv[j * 9 + head] + accS[mblk][u];
                    s = fminf(5.f, fmaxf(-5.f, s));
                    const float p1 = __expf(s) * am4[mblk][u >> 1];
                    sPE[cn * 257 + j] = make_float2(p1, accE[mblk][u]);
                }
            }
        }
        __syncthreads();

        // phase 2: column reductions (thread: col c = t&63, j-group g = t>>6)
        {
            const int c = t & 63, g = t >> 6;
            const int hk = h0 + c;
            float den = 0.f, o = 0.f;
            const float* __restrict__ Vp = g_V + ((size_t)b * NN + g * 64) * HD + hk;
            #pragma unroll 8
            for (int jj = 0; jj < 64; jj++) {
                const int j2 = g * 64 + jj;
                const float2 pe = sPE[c * 257 + j2];
                den += pe.x;
                o = fmaf(pe.x * sAmv[j2], Vp[(size_t)jj * HD] + pe.y, o);
            }
            sRedD[g * 64 + c] = den;
            sRedO[g * 64 + c] = o;
        }
        __syncthreads();
        if (t < 64) {
            float D_ = 0.f, O_ = 0.f;
            #pragma unroll
            for (int g4 = 0; g4 < 4; g4++) {
                D_ += sRedD[g4 * 64 + t];
                O_ += sRedO[g4 * 64 + t];
            }
            out[(size_t)bi * HD + h0 + t] = O_ / fmaxf(D_, 1e-6f);
        }
        __syncthreads();   // before staging reuse
    }
}

// ---------------------------------------------------------------------------
// Launch
// ---------------------------------------------------------------------------
extern "C" void kernel_launch(void* const* d_in, const int* in_sizes, int n_in,
                              void* d_out, int out_size)
{
    const float* h    = (const float*)d_in[0];
    const float* e    = (const float*)d_in[1];
    const float* mask = (const float*)d_in[2];
    const float* WQ   = (const float*)d_in[3];
    const float* WK   = (const float*)d_in[4];
    const float* WV   = (const float*)d_in[5];
    const float* WE   = (const float*)d_in[6];
    const float* WE2  = (const float*)d_in[7];
    float* out = (float*)d_out;

    cudaFuncSetAttribute(attn_mma_kernel,
                         cudaFuncAttributeMaxDynamicSharedMemorySize, SMEM_TOTAL);

    qkv_kernel<<<(BB * NN) / QR, 128>>>(h, WQ, WK, WV);
    conv_w_kernel<<<64, 256>>>(WE, WE2);
    attn_mma_kernel<<<BB * NN, 256, SMEM_TOTAL>>>(e, mask, out);
}

// round 11
// speedup vs baseline: 1.5143x; 1.5143x over previous
#include <cuda_runtime.h>
#include <cuda_bf16.h>
#include <cstdint>

#define BB   4
#define NN   256
#define DIN  128
#define DE   64
#define NH   8
#define DK   16
#define HD   128
#define QR   4     // rows per qkv block

// ---------------------------------------------------------------------------
// device-global scratch (no allocations allowed)
// ---------------------------------------------------------------------------
__device__ float g_Q[BB * NN * HD];
__device__ float g_K[BB * NN * HD];   // pre-scaled by DK^-0.5
__device__ float g_V[BB * NN * HD];
__device__ __nv_bfloat16 g_Bhi[2 * HD * DE];  // [n=256][d=64]: n<128 -> WE2 col n, else WE col n-128
__device__ __nv_bfloat16 g_Blo[2 * HD * DE];

#define SMEM_SWZ(off) ((off) ^ (((off) >> 3) & 0x70))

__device__ __forceinline__ uint32_t smem_u32(const void* p) {
    uint32_t a;
    asm("{ .reg .u64 t; cvta.to.shared.u64 t, %1; cvt.u32.u64 %0, t; }" : "=r"(a) : "l"(p));
    return a;
}

// warp-level bf16 MMA (sm_80+, legal on plain sm_103 target)
__device__ __forceinline__ void mma16816(float* c, const uint32_t* a, const uint32_t* b) {
    asm volatile(
        "mma.sync.aligned.m16n8k16.row.col.f32.bf16.bf16.f32 "
        "{%0,%1,%2,%3}, {%4,%5,%6,%7}, {%8,%9}, {%0,%1,%2,%3};"
        : "+f"(c[0]), "+f"(c[1]), "+f"(c[2]), "+f"(c[3])
        : "r"(a[0]), "r"(a[1]), "r"(a[2]), "r"(a[3]), "r"(b[0]), "r"(b[1]));
}
__device__ __forceinline__ void ldmat_x4(uint32_t* r, uint32_t saddr) {
    asm volatile("ldmatrix.sync.aligned.m8n8.x4.shared.b16 {%0,%1,%2,%3}, [%4];"
        : "=r"(r[0]), "=r"(r[1]), "=r"(r[2]), "=r"(r[3]) : "r"(saddr));
}
// split a float2 into bf16x2 hi and bf16x2 lo words
__device__ __forceinline__ void split2(float2 v, uint32_t& hi, uint32_t& lo) {
    const __nv_bfloat16 hx = __float2bfloat16(v.x);
    const __nv_bfloat16 hy = __float2bfloat16(v.y);
    const __nv_bfloat16 lx = __float2bfloat16(v.x - __bfloat162float(hx));
    const __nv_bfloat16 ly = __float2bfloat16(v.y - __bfloat162float(hy));
    __nv_bfloat162 h2; h2.x = hx; h2.y = hy;
    __nv_bfloat162 l2; l2.x = lx; l2.y = ly;
    hi = *(uint32_t*)&h2;
    lo = *(uint32_t*)&l2;
}

// ---------------------------------------------------------------------------
// SMEM layout (dynamic) — small: 2 CTAs/SM
// ---------------------------------------------------------------------------
#define SM_B       0                       // Whi 32768, Wlo at +32768 -> [0, 65536)
#define SM_QK      65536                   // 256*9*4 = 9216
#define SM_AM      74752                   // 256*4
#define SM_QROW    75776                   // 128*4
#define SM_WDEN    76288                   // 8*128*4 = 4096 (per-warp denom partials)
#define SM_WOUT    80384                   // 8*128*4 = 4096 (per-warp out partials)
#define SMEM_TOTAL 84480

// ---------------------------------------------------------------------------
// Kernel 1: QKV projection. QR rows/block, 256 threads (d-dim split in two).
// ---------------------------------------------------------------------------
__global__ __launch_bounds__(256) void qkv_kernel(
    const float* __restrict__ h,
    const float* __restrict__ WQ,
    const float* __restrict__ WK,
    const float* __restrict__ WV)
{
    __shared__ float sh[QR][DIN];
    __shared__ float spart[3][QR][HD];
    const int rb = blockIdx.x * QR;
    const int t  = threadIdx.x;          // 0..255
    const int tc = t & 127;              // output column
    const int dh = t >> 7;               // d-half

    ((float*)sh)[t]       = h[rb * DIN + t];
    ((float*)sh)[t + 256] = h[rb * DIN + t + 256];
    __syncthreads();

    float q[QR], k[QR], v[QR];
    #pragma unroll
    for (int r = 0; r < QR; r++) { q[r] = 0.f; k[r] = 0.f; v[r] = 0.f; }

    const int d0 = dh * 64;
    #pragma unroll 8
    for (int d = 0; d < 64; d++) {
        const float wq = WQ[(d0 + d) * HD + tc];
        const float wk = WK[(d0 + d) * HD + tc];
        const float wv = WV[(d0 + d) * HD + tc];
        #pragma unroll
        for (int r = 0; r < QR; r++) {
            const float hx = sh[r][d0 + d];
            q[r] = fmaf(hx, wq, q[r]);
            k[r] = fmaf(hx, wk, k[r]);
            v[r] = fmaf(hx, wv, v[r]);
        }
    }
    if (dh == 1) {
        #pragma unroll
        for (int r = 0; r < QR; r++) {
            spart[0][r][tc] = q[r];
            spart[1][r][tc] = k[r];
            spart[2][r][tc] = v[r];
        }
    }
    __syncthreads();
    if (dh == 0) {
        #pragma unroll
        for (int r = 0; r < QR; r++) {
            g_Q[(rb + r) * HD + tc] = q[r] + spart[0][r][tc];
            g_K[(rb + r) * HD + tc] = (k[r] + spart[1][r][tc]) * 0.25f;
            g_V[(rb + r) * HD + tc] = v[r] + spart[2][r][tc];
        }
    }
}

// ---------------------------------------------------------------------------
// Kernel 2: weight split -> layout [n][d], bf16 hi/lo
// ---------------------------------------------------------------------------
__global__ __launch_bounds__(256) void conv_w_kernel(
    const float* __restrict__ WE, const float* __restrict__ WE2)
{
    const int idx = blockIdx.x * 256 + threadIdx.x;   // 0..16383
    const int n = idx >> 6, d = idx & 63;
    const float* W = (n < HD) ? WE2 : WE;
    const float w = W[d * HD + (n & (HD - 1))];
    const __nv_bfloat16 hi = __float2bfloat16(w);
    const __nv_bfloat16 lo = __float2bfloat16(w - __bfloat162float(hi));
    g_Bhi[idx] = hi;
    g_Blo[idx] = lo;
}

// ---------------------------------------------------------------------------
// Kernel 3: fused HMMA attention, fragment-domain reduction.
//   One CTA per (b,i), 256 threads (8 warps), 2 CTAs/SM.
//   S[256j x 256n] = [e_hi|e_lo|e_hi] @ [Whi;Whi;Wlo]^T  (3-term bf16 split)
//   Per cg: HMMA -> exp -> p*(V+E) and denom reduced via shfl, per-warp slices.
// ---------------------------------------------------------------------------
__global__ __launch_bounds__(256, 2)
void attn_mma_kernel(
    const float* __restrict__ e,
    const float* __restrict__ mask,
    float* __restrict__ out)
{
    extern __shared__ char smem[];
    const uint32_t sbase = smem_u32(smem);
    const int t   = threadIdx.x;
    const int wid = t >> 5;
    const int lid = t & 31;
    const int gid = lid >> 2;        // 0..7
    const int tig = lid & 3;         // 0..3
    const int bi  = blockIdx.x;
    const int b   = bi >> 8;
    const int i   = bi & 255;

    float* sQKv  = (float*)(smem + SM_QK);
    float* sAmv  = (float*)(smem + SM_AM);
    float* sQrow = (float*)(smem + SM_QROW);
    float* sWden = (float*)(smem + SM_WDEN);
    float* sWout = (float*)(smem + SM_WOUT);

    // ---- load W (bf16 hi/lo) into SW128 smem: [256 rows x 128B] ----
    {
        const int ch = t & 7;          // 16B chunk within 128B row
        const int r0 = t >> 3;         // 32 rows per iteration
        #pragma unroll
        for (int it = 0; it < 8; it++) {
            const int row = it * 32 + r0;
            const uint32_t off = SMEM_SWZ(row * 128 + ch * 16);
            *(uint4*)(smem + SM_B + off)         = ((const uint4*)g_Bhi)[row * 8 + ch];
            *(uint4*)(smem + SM_B + 32768 + off) = ((const uint4*)g_Blo)[row * 8 + ch];
        }
    }

    // ---- A fragments direct from gmem: [mblk][kstep][hi/lo][4] ----
    uint32_t afr[2][4][2][4];
    {
        const float* __restrict__ eb = e + (size_t)bi * NN * DE;
        const int jb = wid * 32;
        #pragma unroll
        for (int mblk = 0; mblk < 2; mblk++) {
            const int r0 = jb + mblk * 16 + gid;
            #pragma unroll
            for (int ks = 0; ks < 4; ks++) {
                const int c0 = ks * 16 + tig * 2;
                const float2 v0 = *(const float2*)(eb + r0 * DE + c0);
                const float2 v1 = *(const float2*)(eb + (r0 + 8) * DE + c0);
                const float2 v2 = *(const float2*)(eb + r0 * DE + c0 + 8);
                const float2 v3 = *(const float2*)(eb + (r0 + 8) * DE + c0 + 8);
                split2(v0, afr[mblk][ks][0][0], afr[mblk][ks][1][0]);
                split2(v1, afr[mblk][ks][0][1], afr[mblk][ks][1][1]);
                split2(v2, afr[mblk][ks][0][2], afr[mblk][ks][1][2]);
                split2(v3, afr[mblk][ks][0][3], afr[mblk][ks][1][3]);
            }
        }
    }

    // ---- mask products + Q row ----
    sAmv[t] = mask[b * NN + i] * mask[b * NN + t];
    if (t < HD) sQrow[t] = g_Q[(size_t)bi * HD + t];
    __syncthreads();

    // ---- QK scores (fp32 exact): thread t owns j = t ----
    {
        const float4* __restrict__ Kp = (const float4*)(g_K + ((size_t)b * NN + t) * HD);
        #pragma unroll
        for (int hh = 0; hh < NH; hh++) {
            float s_ = 0.f;
            #pragma unroll
            for (int kk = 0; kk < DK / 4; kk++) {
                const float4 kv = Kp[hh * (DK / 4) + kk];
                const float* qp = &sQrow[hh * DK + kk * 4];
                s_ += kv.x * qp[0] + kv.y * qp[1] + kv.z * qp[2] + kv.w * qp[3];
            }
            sQKv[t * 9 + hh] = s_;
        }
    }
    __syncthreads();

    float am4[2][2];
    #pragma unroll
    for (int mblk = 0; mblk < 2; mblk++) {
        am4[mblk][0] = sAmv[wid * 32 + mblk * 16 + gid];
        am4[mblk][1] = sAmv[wid * 32 + mblk * 16 + gid + 8];
    }

    // ldmatrix lane roles: sel 0/1 -> score cols (k0-7 / k8-15), sel 2/3 -> E cols
    const int sel = lid >> 3;
    const int r8  = lid & 7;
    const int nsel = (sel >= 2) ? 128 : 0;
    const uint32_t koff16 = (sel & 1) * 16;
    const float* __restrict__ Vb = g_V + (size_t)b * NN * HD;

    // ---- main loop: 16 col-groups, no block barriers ----
    for (int h0 = 0; h0 < HD; h0 += 64) {
        #pragma unroll 1
        for (int cg = 0; cg < 8; cg++) {
            float accS[2][4] = {{0.f,0.f,0.f,0.f},{0.f,0.f,0.f,0.f}};
            float accE[2][4] = {{0.f,0.f,0.f,0.f},{0.f,0.f,0.f,0.f}};
            const int nrow = h0 + cg * 8 + r8 + nsel;
            const uint32_t rowbase = sbase + SM_B + (uint32_t)nrow * 128;
            const uint32_t xkey = ((uint32_t)nrow & 7) << 4;
            #pragma unroll
            for (int ks = 0; ks < 4; ks++) {
                const uint32_t addr = rowbase + (((uint32_t)ks * 32 + koff16) ^ xkey);
                uint32_t bh[4], bl[4];
                ldmat_x4(bh, addr);
                ldmat_x4(bl, addr + 32768);
                #pragma unroll
                for (int mblk = 0; mblk < 2; mblk++) {
                    mma16816(accS[mblk], afr[mblk][ks][0], bh + 0);  // Ahi*Whi
                    mma16816(accS[mblk], afr[mblk][ks][1], bh + 0);  // Alo*Whi
                    mma16816(accS[mblk], afr[mblk][ks][0], bl + 0);  // Ahi*Wlo
                    mma16816(accE[mblk], afr[mblk][ks][0], bh + 2);
                    mma16816(accE[mblk], afr[mblk][ks][1], bh + 2);
                    mma16816(accE[mblk], afr[mblk][ks][0], bl + 2);
                }
            }
            // fragment epilogue: exp + V/E accumulation, reduced over gid lanes
            float den0 = 0.f, den1 = 0.f, out0 = 0.f, out1 = 0.f;
            #pragma unroll
            for (int mblk = 0; mblk < 2; mblk++) {
                #pragma unroll
                for (int u = 0; u < 4; u++) {
                    const int j  = wid * 32 + mblk * 16 + gid + (u >> 1) * 8;
                    const int cn = cg * 8 + tig * 2 + (u & 1);
                    const int hk = h0 + cn;
                    float s = sQKv[j * 9 + (hk >> 4)] + accS[mblk][u];
                    s = fminf(5.f, fmaxf(-5.f, s));
                    const float am = am4[mblk][u >> 1];
                    const float p1 = __expf(s) * am;
                    const float vv = Vb[(size_t)j * HD + hk];
                    const float ct = p1 * am * (vv + accE[mblk][u]);
                    if (u & 1) { den1 += p1; out1 += ct; }
                    else       { den0 += p1; out0 += ct; }
                }
            }
            #pragma unroll
            for (int m_ = 4; m_ <= 16; m_ <<= 1) {
                den0 += __shfl_xor_sync(0xffffffffu, den0, m_);
                den1 += __shfl_xor_sync(0xffffffffu, den1, m_);
                out0 += __shfl_xor_sync(0xffffffffu, out0, m_);
                out1 += __shfl_xor_sync(0xffffffffu, out1, m_);
            }
            if (gid == 0) {
                const int c = h0 + cg * 8 + tig * 2;
                sWden[wid * 128 + c]     = den0;
                sWden[wid * 128 + c + 1] = den1;
                sWout[wid * 128 + c]     = out0;
                sWout[wid * 128 + c + 1] = out1;
            }
        }
    }
    __syncthreads();

    // ---- final cross-warp combine ----
    if (t < HD) {
        float D_ = 0.f, O_ = 0.f;
        #pragma unroll
        for (int w = 0; w < 8; w++) {
            D_ += sWden[w * 128 + t];
            O_ += sWout[w * 128 + t];
        }
        out[(size_t)bi * HD + t] = O_ / fmaxf(D_, 1e-6f);
    }
}

// ---------------------------------------------------------------------------
// Launch
// ---------------------------------------------------------------------------
extern "C" void kernel_launch(void* const* d_in, const int* in_sizes, int n_in,
                              void* d_out, int out_size)
{
    const float* h    = (const float*)d_in[0];
    const float* e    = (const float*)d_in[1];
    const float* mask = (const float*)d_in[2];
    const float* WQ   = (const float*)d_in[3];
    const float* WK   = (const float*)d_in[4];
    const float* WV   = (const float*)d_in[5];
    const float* WE   = (const float*)d_in[6];
    const float* WE2  = (const float*)d_in[7];
    float* out = (float*)d_out;

    cudaFuncSetAttribute(attn_mma_kernel,
                         cudaFuncAttributeMaxDynamicSharedMemorySize, SMEM_TOTAL);

    qkv_kernel<<<(BB * NN) / QR, 256>>>(h, WQ, WK, WV);
    conv_w_kernel<<<64, 256>>>(WE, WE2);
    attn_mma_kernel<<<BB * NN, 256, SMEM_TOTAL>>>(e, mask, out);
}

// round 14
// speedup vs baseline: 1.7807x; 1.1760x over previous
#include <cuda_runtime.h>
#include <cuda_bf16.h>
#include <cuda_fp16.h>
#include <cstdint>

#define BB   4
#define NN   256
#define DIN  128
#define DE   64
#define NH   8
#define DK   16
#define HD   128
#define QR   4     // rows per qkv block
#define QKV_BLOCKS ((BB * NN) / QR)   // 256

// ---------------------------------------------------------------------------
// device-global scratch (no allocations allowed)
// ---------------------------------------------------------------------------
__device__ float g_Q[BB * NN * HD];
__device__ float g_K[BB * NN * HD];   // pre-scaled by DK^-0.5
__device__ float g_V[BB * NN * HD];
__device__ __half g_Bh[2 * HD * DE];  // fp16 W_hi: [n=256][d=64]; n<128 -> WE2 col n, else WE col n-128

#define SMEM_SWZ(off) ((off) ^ (((off) >> 3) & 0x70))

__device__ __forceinline__ uint32_t smem_u32(const void* p) {
    uint32_t a;
    asm("{ .reg .u64 t; cvta.to.shared.u64 t, %1; cvt.u32.u64 %0, t; }" : "=r"(a) : "l"(p));
    return a;
}

// warp-level fp16 MMA (sm_80+, legal on plain sm_103 target)
__device__ __forceinline__ void mma16816(float* c, const uint32_t* a, const uint32_t* b) {
    asm volatile(
        "mma.sync.aligned.m16n8k16.row.col.f32.f16.f16.f32 "
        "{%0,%1,%2,%3}, {%4,%5,%6,%7}, {%8,%9}, {%0,%1,%2,%3};"
        : "+f"(c[0]), "+f"(c[1]), "+f"(c[2]), "+f"(c[3])
        : "r"(a[0]), "r"(a[1]), "r"(a[2]), "r"(a[3]), "r"(b[0]), "r"(b[1]));
}
__device__ __forceinline__ void ldmat_x4(uint32_t* r, uint32_t saddr) {
    asm volatile("ldmatrix.sync.aligned.m8n8.x4.shared.b16 {%0,%1,%2,%3}, [%4];"
        : "=r"(r[0]), "=r"(r[1]), "=r"(r[2]), "=r"(r[3]) : "r"(saddr));
}
// split a float2 into fp16x2 hi and fp16x2 lo words (hi+lo == v to ~2^-22)
__device__ __forceinline__ void split2h(float2 v, uint32_t& hi, uint32_t& lo) {
    const __half hx = __float2half(v.x);
    const __half hy = __float2half(v.y);
    const __half lx = __float2half(v.x - __half2float(hx));
    const __half ly = __float2half(v.y - __half2float(hy));
    __half2 h2; h2.x = hx; h2.y = hy;
    __half2 l2; l2.x = lx; l2.y = ly;
    hi = *(uint32_t*)&h2;
    lo = *(uint32_t*)&l2;
}

// ---------------------------------------------------------------------------
// SMEM layout (dynamic) — 2 CTAs/SM
// ---------------------------------------------------------------------------
#define SM_B       0                       // W_hi fp16 swizzled: 256 rows x 128B = 32768
#define SM_QK      32768                   // 256*9*4 = 9216
#define SM_AM      41984                   // 256*4
#define SM_QROW    43008                   // 128*4
#define SM_WDEN    43520                   // 8*128*4 = 4096
#define SM_WOUT    47616                   // 8*128*4 = 4096
#define SMEM_TOTAL 51712

// ---------------------------------------------------------------------------
// Kernel 1: QKV projection (+ fused weight-convert blocks).
//   qkv: QR rows/block, 256 threads = 64 col-pairs x 4 d-quarters.
//   conv: blocks >= QKV_BLOCKS build g_Bh (fp16 W_hi, [n][d] layout).
// ---------------------------------------------------------------------------
__global__ __launch_bounds__(256) void prep_kernel(
    const float* __restrict__ h,
    const float* __restrict__ WQ,
    const float* __restrict__ WK,
    const float* __restrict__ WV,
    const float* __restrict__ WE,
    const float* __restrict__ WE2)
{
    if (blockIdx.x >= QKV_BLOCKS) {
        const int idx = (blockIdx.x - QKV_BLOCKS) * 256 + threadIdx.x;  // 0..16383
        const int n = idx >> 6, d = idx & 63;
        const float* W = (n < HD) ? WE2 : WE;
        g_Bh[idx] = __float2half(W[d * HD + (n & (HD - 1))]);
        return;
    }

    __shared__ float sh[QR][DIN];
    __shared__ float sp[3][3][QR][HD];   // partials for d-quarters 1..3
    const int rb = blockIdx.x * QR;
    const int t  = threadIdx.x;
    const int cp = t & 63;               // col pair -> cols 2cp, 2cp+1
    const int dq = t >> 6;               // d quarter

    ((float*)sh)[t]       = h[rb * DIN + t];
    ((float*)sh)[t + 256] = h[rb * DIN + t + 256];
    __syncthreads();

    float acc[3][QR][2];
    #pragma unroll
    for (int m = 0; m < 3; m++)
        #pragma unroll
        for (int r = 0; r < QR; r++) { acc[m][r][0] = 0.f; acc[m][r][1] = 0.f; }

    const int d0 = dq * 32;
    #pragma unroll 8
    for (int d = 0; d < 32; d++) {
        const float2 wq = *(const float2*)&WQ[(d0 + d) * HD + 2 * cp];
        const float2 wk = *(const float2*)&WK[(d0 + d) * HD + 2 * cp];
        const float2 wv = *(const float2*)&WV[(d0 + d) * HD + 2 * cp];
        #pragma unroll
        for (int r = 0; r < QR; r++) {
            const float hx = sh[r][d0 + d];
            acc[0][r][0] = fmaf(hx, wq.x, acc[0][r][0]);
            acc[0][r][1] = fmaf(hx, wq.y, acc[0][r][1]);
            acc[1][r][0] = fmaf(hx, wk.x, acc[1][r][0]);
            acc[1][r][1] = fmaf(hx, wk.y, acc[1][r][1]);
            acc[2][r][0] = fmaf(hx, wv.x, acc[2][r][0]);
            acc[2][r][1] = fmaf(hx, wv.y, acc[2][r][1]);
        }
    }
    if (dq > 0) {
        #pragma unroll
        for (int m = 0; m < 3; m++)
            #pragma unroll
            for (int r = 0; r < QR; r++)
                *(float2*)&sp[m][dq - 1][r][2 * cp] = make_float2(acc[m][r][0], acc[m][r][1]);
    }
    __syncthreads();
    if (dq == 0) {
        #pragma unroll
        for (int r = 0; r < QR; r++) {
            float qx = acc[0][r][0], qy = acc[0][r][1];
            float kx = acc[1][r][0], ky = acc[1][r][1];
            float vx = acc[2][r][0], vy = acc[2][r][1];
            #pragma unroll
            for (int s = 0; s < 3; s++) {
                qx += sp[0][s][r][2 * cp]; qy += sp[0][s][r][2 * cp + 1];
                kx += sp[1][s][r][2 * cp]; ky += sp[1][s][r][2 * cp + 1];
                vx += sp[2][s][r][2 * cp]; vy += sp[2][s][r][2 * cp + 1];
            }
            *(float2*)&g_Q[(rb + r) * HD + 2 * cp] = make_float2(qx, qy);
            *(float2*)&g_K[(rb + r) * HD + 2 * cp] = make_float2(kx * 0.25f, ky * 0.25f);
            *(float2*)&g_V[(rb + r) * HD + 2 * cp] = make_float2(vx, vy);
        }
    }
}

// ---------------------------------------------------------------------------
// Kernel 2: fused HMMA attention, fragment-domain reduction.
//   One CTA per (b,i), 256 threads (8 warps), 2 CTAs/SM.
//   S[256j x 256n] = (e_hi + e_lo) @ W_hi^T   (fp16 2-term split, fp32 accum)
//   cols n<128: E2 scores; n>=128: E.
// ---------------------------------------------------------------------------
__global__ __launch_bounds__(256, 2)
void attn_mma_kernel(
    const float* __restrict__ e,
    const float* __restrict__ mask,
    float* __restrict__ out)
{
    extern __shared__ char smem[];
    const uint32_t sbase = smem_u32(smem);
    const int t   = threadIdx.x;
    const int wid = t >> 5;
    const int lid = t & 31;
    const int gid = lid >> 2;        // 0..7
    const int tig = lid & 3;         // 0..3
    const int bi  = blockIdx.x;
    const int b   = bi >> 8;
    const int i   = bi & 255;

    float* sQKv  = (float*)(smem + SM_QK);
    float* sAmv  = (float*)(smem + SM_AM);
    float* sQrow = (float*)(smem + SM_QROW);
    float* sWden = (float*)(smem + SM_WDEN);
    float* sWout = (float*)(smem + SM_WOUT);

    // ---- load W_hi (fp16) into SW128 smem: [256 rows x 128B] ----
    {
        const int ch = t & 7;          // 16B chunk within 128B row
        const int r0 = t >> 3;         // 32 rows per iteration
        #pragma unroll
        for (int it = 0; it < 8; it++) {
            const int row = it * 32 + r0;
            const uint32_t off = SMEM_SWZ(row * 128 + ch * 16);
            *(uint4*)(smem + SM_B + off) = ((const uint4*)g_Bh)[row * 8 + ch];
        }
    }

    // ---- A fragments direct from gmem: [mblk][kstep][hi/lo][4] (fp16) ----
    uint32_t afr[2][4][2][4];
    {
        const float* __restrict__ eb = e + (size_t)bi * NN * DE;
        const int jb = wid * 32;
        #pragma unroll
        for (int mblk = 0; mblk < 2; mblk++) {
            const int r0 = jb + mblk * 16 + gid;
            #pragma unroll
            for (int ks = 0; ks < 4; ks++) {
                const int c0 = ks * 16 + tig * 2;
                const float2 v0 = *(const float2*)(eb + r0 * DE + c0);
                const float2 v1 = *(const float2*)(eb + (r0 + 8) * DE + c0);
                const float2 v2 = *(const float2*)(eb + r0 * DE + c0 + 8);
                const float2 v3 = *(const float2*)(eb + (r0 + 8) * DE + c0 + 8);
                split2h(v0, afr[mblk][ks][0][0], afr[mblk][ks][1][0]);
                split2h(v1, afr[mblk][ks][0][1], afr[mblk][ks][1][1]);
                split2h(v2, afr[mblk][ks][0][2], afr[mblk][ks][1][2]);
                split2h(v3, afr[mblk][ks][0][3], afr[mblk][ks][1][3]);
            }
        }
    }

    // ---- mask products + Q row ----
    sAmv[t] = mask[b * NN + i] * mask[b * NN + t];
    if (t < HD) sQrow[t] = g_Q[(size_t)bi * HD + t];
    __syncthreads();

    // ---- QK scores (fp32 exact): thread t owns j = t ----
    {
        const float4* __restrict__ Kp = (const float4*)(g_K + ((size_t)b * NN + t) * HD);
        #pragma unroll
        for (int hh = 0; hh < NH; hh++) {
            float s_ = 0.f;
            #pragma unroll
            for (int kk = 0; kk < DK / 4; kk++) {
                const float4 kv = Kp[hh * (DK / 4) + kk];
                const float* qp = &sQrow[hh * DK + kk * 4];
                s_ += kv.x * qp[0] + kv.y * qp[1] + kv.z * qp[2] + kv.w * qp[3];
            }
            sQKv[t * 9 + hh] = s_;
        }
    }
    __syncthreads();

    float am4[2][2];
    #pragma unroll
    for (int mblk = 0; mblk < 2; mblk++) {
        am4[mblk][0] = sAmv[wid * 32 + mblk * 16 + gid];
        am4[mblk][1] = sAmv[wid * 32 + mblk * 16 + gid + 8];
    }

    // ldmatrix lane roles: sel 0/1 -> score cols (k0-7 / k8-15), sel 2/3 -> E cols
    const int sel = lid >> 3;
    const int r8  = lid & 7;
    const int nsel = (sel >= 2) ? 128 : 0;
    const uint32_t koff16 = (sel & 1) * 16;
    const float* __restrict__ Vb = g_V + (size_t)b * NN * HD;

    // ---- main loop: 16 col-groups, no block barriers ----
    for (int h0 = 0; h0 < HD; h0 += 64) {
        #pragma unroll 1
        for (int cg = 0; cg < 8; cg++) {
            float accS[2][4] = {{0.f,0.f,0.f,0.f},{0.f,0.f,0.f,0.f}};
            float accE[2][4] = {{0.f,0.f,0.f,0.f},{0.f,0.f,0.f,0.f}};
            const int nrow = h0 + cg * 8 + r8 + nsel;
            const uint32_t rowbase = sbase + SM_B + (uint32_t)nrow * 128;
            const uint32_t xkey = ((uint32_t)nrow & 7) << 4;
            #pragma unroll
            for (int ks = 0; ks < 4; ks++) {
                const uint32_t addr = rowbase + (((uint32_t)ks * 32 + koff16) ^ xkey);
                uint32_t bh[4];
                ldmat_x4(bh, addr);
                #pragma unroll
                for (int mblk = 0; mblk < 2; mblk++) {
                    mma16816(accS[mblk], afr[mblk][ks][0], bh + 0);  // e_hi @ W_hi
                    mma16816(accS[mblk], afr[mblk][ks][1], bh + 0);  // e_lo @ W_hi
                    mma16816(accE[mblk], afr[mblk][ks][0], bh + 2);
                    mma16816(accE[mblk], afr[mblk][ks][1], bh + 2);
                }
            }
            // fragment epilogue: exp + V/E accumulation, reduced over gid lanes
            float den0 = 0.f, den1 = 0.f, out0 = 0.f, out1 = 0.f;
            #pragma unroll
            for (int mblk = 0; mblk < 2; mblk++) {
                #pragma unroll
                for (int u = 0; u < 4; u++) {
                    const int j  = wid * 32 + mblk * 16 + gid + (u >> 1) * 8;
                    const int cn = cg * 8 + tig * 2 + (u & 1);
                    const int hk = h0 + cn;
                    float s = sQKv[j * 9 + (hk >> 4)] + accS[mblk][u];
                    s = fminf(5.f, fmaxf(-5.f, s));
                    const float am = am4[mblk][u >> 1];
                    const float p1 = __expf(s) * am;
                    const float vv = Vb[(size_t)j * HD + hk];
                    const float ct = p1 * am * (vv + accE[mblk][u]);
                    if (u & 1) { den1 += p1; out1 += ct; }
                    else       { den0 += p1; out0 += ct; }
                }
            }
            #pragma unroll
            for (int m_ = 4; m_ <= 16; m_ <<= 1) {
                den0 += __shfl_xor_sync(0xffffffffu, den0, m_);
                den1 += __shfl_xor_sync(0xffffffffu, den1, m_);
                out0 += __shfl_xor_sync(0xffffffffu, out0, m_);
                out1 += __shfl_xor_sync(0xffffffffu, out1, m_);
            }
            if (gid == 0) {
                const int c = h0 + cg * 8 + tig * 2;
                sWden[wid * 128 + c]     = den0;
                sWden[wid * 128 + c + 1] = den1;
                sWout[wid * 128 + c]     = out0;
                sWout[wid * 128 + c + 1] = out1;
            }
        }
    }
    __syncthreads();

    // ---- final cross-warp combine ----
    if (t < HD) {
        float D_ = 0.f, O_ = 0.f;
        #pragma unroll
        for (int w = 0; w < 8; w++) {
            D_ += sWden[w * 128 + t];
            O_ += sWout[w * 128 + t];
        }
        out[(size_t)bi * HD + t] = O_ / fmaxf(D_, 1e-6f);
    }
}

// ---------------------------------------------------------------------------
// Launch
// ---------------------------------------------------------------------------
extern "C" void kernel_launch(void* const* d_in, const int* in_sizes, int n_in,
                              void* d_out, int out_size)
{
    const float* h    = (const float*)d_in[0];
    const float* e    = (const float*)d_in[1];
    const float* mask = (const float*)d_in[2];
    const float* WQ   = (const float*)d_in[3];
    const float* WK   = (const float*)d_in[4];
    const float* WV   = (const float*)d_in[5];
    const float* WE   = (const float*)d_in[6];
    const float* WE2  = (const float*)d_in[7];
    float* out = (float*)d_out;

    cudaFuncSetAttribute(attn_mma_kernel,
                         cudaFuncAttributeMaxDynamicSharedMemorySize, SMEM_TOTAL);

    prep_kernel<<<QKV_BLOCKS + 64, 256>>>(h, WQ, WK, WV, WE, WE2);
    attn_mma_kernel<<<BB * NN, 256, SMEM_TOTAL>>>(e, mask, out);
}

// round 15
// speedup vs baseline: 1.8162x; 1.0199x over previous
#include <cuda_runtime.h>
#include <cuda_bf16.h>
#include <cuda_fp16.h>
#include <cstdint>

#define BB   4
#define NN   256
#define DIN  128
#define DE   64
#define NH   8
#define DK   16
#define HD   128
#define QR   4     // rows per qkv block
#define QKV_BLOCKS ((BB * NN) / QR)   // 256

// ---------------------------------------------------------------------------
// device-global scratch (no allocations allowed)
// ---------------------------------------------------------------------------
__device__ float g_Q[BB * NN * HD];
__device__ float g_K[BB * NN * HD];   // pre-scaled by DK^-0.5
__device__ float g_V[BB * NN * HD];
__device__ __half g_Bh[2 * HD * DE];  // fp16 W_hi: [n=256][d=64]; n<128 -> WE2 col n, else WE col n-128

#define SMEM_SWZ(off) ((off) ^ (((off) >> 3) & 0x70))

__device__ __forceinline__ uint32_t smem_u32(const void* p) {
    uint32_t a;
    asm("{ .reg .u64 t; cvta.to.shared.u64 t, %1; cvt.u32.u64 %0, t; }" : "=r"(a) : "l"(p));
    return a;
}

// warp-level fp16 MMA (sm_80+, legal on plain sm_103 target)
__device__ __forceinline__ void mma16816(float* c, const uint32_t* a, const uint32_t* b) {
    asm volatile(
        "mma.sync.aligned.m16n8k16.row.col.f32.f16.f16.f32 "
        "{%0,%1,%2,%3}, {%4,%5,%6,%7}, {%8,%9}, {%0,%1,%2,%3};"
        : "+f"(c[0]), "+f"(c[1]), "+f"(c[2]), "+f"(c[3])
        : "r"(a[0]), "r"(a[1]), "r"(a[2]), "r"(a[3]), "r"(b[0]), "r"(b[1]));
}
__device__ __forceinline__ void ldmat_x4(uint32_t* r, uint32_t saddr) {
    asm volatile("ldmatrix.sync.aligned.m8n8.x4.shared.b16 {%0,%1,%2,%3}, [%4];"
        : "=r"(r[0]), "=r"(r[1]), "=r"(r[2]), "=r"(r[3]) : "r"(saddr));
}
// split a float2 into fp16x2 hi and fp16x2 lo words (hi+lo == v to ~2^-22)
__device__ __forceinline__ void split2h(float2 v, uint32_t& hi, uint32_t& lo) {
    const __half hx = __float2half(v.x);
    const __half hy = __float2half(v.y);
    const __half lx = __float2half(v.x - __half2float(hx));
    const __half ly = __float2half(v.y - __half2float(hy));
    __half2 h2; h2.x = hx; h2.y = hy;
    __half2 l2; l2.x = lx; l2.y = ly;
    hi = *(uint32_t*)&h2;
    lo = *(uint32_t*)&l2;
}

// ---------------------------------------------------------------------------
// SMEM layout (dynamic) — 2 CTAs/SM
// ---------------------------------------------------------------------------
#define SM_B       0                       // W_hi fp16 swizzled: 256 rows x 128B = 32768
#define SM_QK      32768                   // 256*9*4 = 9216
#define SM_AM      41984                   // 256*4
#define SM_QROW    43008                   // 128*4
#define SM_WDEN    43520                   // 8*128*4 = 4096
#define SM_WOUT    47616                   // 8*128*4 = 4096
#define SMEM_TOTAL 51712

// ---------------------------------------------------------------------------
// Kernel 1: QKV projection (+ fused weight-convert blocks).
// ---------------------------------------------------------------------------
__global__ __launch_bounds__(256) void prep_kernel(
    const float* __restrict__ h,
    const float* __restrict__ WQ,
    const float* __restrict__ WK,
    const float* __restrict__ WV,
    const float* __restrict__ WE,
    const float* __restrict__ WE2)
{
    if (blockIdx.x >= QKV_BLOCKS) {
        const int idx = (blockIdx.x - QKV_BLOCKS) * 256 + threadIdx.x;  // 0..16383
        const int n = idx >> 6, d = idx & 63;
        const float* W = (n < HD) ? WE2 : WE;
        g_Bh[idx] = __float2half(W[d * HD + (n & (HD - 1))]);
        return;
    }

    __shared__ float sh[QR][DIN];
    __shared__ float sp[3][3][QR][HD];   // partials for d-quarters 1..3
    const int rb = blockIdx.x * QR;
    const int t  = threadIdx.x;
    const int cp = t & 63;               // col pair -> cols 2cp, 2cp+1
    const int dq = t >> 6;               // d quarter

    ((float*)sh)[t]       = h[rb * DIN + t];
    ((float*)sh)[t + 256] = h[rb * DIN + t + 256];
    __syncthreads();

    float acc[3][QR][2];
    #pragma unroll
    for (int m = 0; m < 3; m++)
        #pragma unroll
        for (int r = 0; r < QR; r++) { acc[m][r][0] = 0.f; acc[m][r][1] = 0.f; }

    const int d0 = dq * 32;
    #pragma unroll 8
    for (int d = 0; d < 32; d++) {
        const float2 wq = *(const float2*)&WQ[(d0 + d) * HD + 2 * cp];
        const float2 wk = *(const float2*)&WK[(d0 + d) * HD + 2 * cp];
        const float2 wv = *(const float2*)&WV[(d0 + d) * HD + 2 * cp];
        #pragma unroll
        for (int r = 0; r < QR; r++) {
            const float hx = sh[r][d0 + d];
            acc[0][r][0] = fmaf(hx, wq.x, acc[0][r][0]);
            acc[0][r][1] = fmaf(hx, wq.y, acc[0][r][1]);
            acc[1][r][0] = fmaf(hx, wk.x, acc[1][r][0]);
            acc[1][r][1] = fmaf(hx, wk.y, acc[1][r][1]);
            acc[2][r][0] = fmaf(hx, wv.x, acc[2][r][0]);
            acc[2][r][1] = fmaf(hx, wv.y, acc[2][r][1]);
        }
    }
    if (dq > 0) {
        #pragma unroll
        for (int m = 0; m < 3; m++)
            #pragma unroll
            for (int r = 0; r < QR; r++)
                *(float2*)&sp[m][dq - 1][r][2 * cp] = make_float2(acc[m][r][0], acc[m][r][1]);
    }
    __syncthreads();
    if (dq == 0) {
        #pragma unroll
        for (int r = 0; r < QR; r++) {
            float qx = acc[0][r][0], qy = acc[0][r][1];
            float kx = acc[1][r][0], ky = acc[1][r][1];
            float vx = acc[2][r][0], vy = acc[2][r][1];
            #pragma unroll
            for (int s = 0; s < 3; s++) {
                qx += sp[0][s][r][2 * cp]; qy += sp[0][s][r][2 * cp + 1];
                kx += sp[1][s][r][2 * cp]; ky += sp[1][s][r][2 * cp + 1];
                vx += sp[2][s][r][2 * cp]; vy += sp[2][s][r][2 * cp + 1];
            }
            *(float2*)&g_Q[(rb + r) * HD + 2 * cp] = make_float2(qx, qy);
            *(float2*)&g_K[(rb + r) * HD + 2 * cp] = make_float2(kx * 0.25f, ky * 0.25f);
            *(float2*)&g_V[(rb + r) * HD + 2 * cp] = make_float2(vx, vy);
        }
    }
}

// ---------------------------------------------------------------------------
// Kernel 2: fused HMMA attention, fragment-domain reduction.
//   One CTA per (b,i), 256 threads (8 warps), 2 CTAs/SM.
//   S[256j x 256n] = (e_hi + e_lo) @ W_hi^T   (fp16 2-term split, fp32 accum)
//   cols n<128: E2 scores; n>=128: E.
// ---------------------------------------------------------------------------
__global__ __launch_bounds__(256, 2)
void attn_mma_kernel(
    const float* __restrict__ e,
    const float* __restrict__ mask,
    float* __restrict__ out)
{
    extern __shared__ char smem[];
    const uint32_t sbase = smem_u32(smem);
    const int t   = threadIdx.x;
    const int wid = t >> 5;
    const int lid = t & 31;
    const int gid = lid >> 2;        // 0..7
    const int tig = lid & 3;         // 0..3
    const int bi  = blockIdx.x;
    const int b   = bi >> 8;
    const int i   = bi & 255;

    float* sQKv  = (float*)(smem + SM_QK);
    float* sAmv  = (float*)(smem + SM_AM);
    float* sQrow = (float*)(smem + SM_QROW);
    float* sWden = (float*)(smem + SM_WDEN);
    float* sWout = (float*)(smem + SM_WOUT);

    // ---- load W_hi (fp16) into SW128 smem: [256 rows x 128B] ----
    {
        const int ch = t & 7;          // 16B chunk within 128B row
        const int r0 = t >> 3;         // 32 rows per iteration
        #pragma unroll
        for (int it = 0; it < 8; it++) {
            const int row = it * 32 + r0;
            const uint32_t off = SMEM_SWZ(row * 128 + ch * 16);
            *(uint4*)(smem + SM_B + off) = ((const uint4*)g_Bh)[row * 8 + ch];
        }
    }

    // ---- A fragments direct from gmem: [mblk][kstep][hi/lo][4] (fp16) ----
    uint32_t afr[2][4][2][4];
    {
        const float* __restrict__ eb = e + (size_t)bi * NN * DE;
        const int jb = wid * 32;
        #pragma unroll
        for (int mblk = 0; mblk < 2; mblk++) {
            const int r0 = jb + mblk * 16 + gid;
            #pragma unroll
            for (int ks = 0; ks < 4; ks++) {
                const int c0 = ks * 16 + tig * 2;
                const float2 v0 = *(const float2*)(eb + r0 * DE + c0);
                const float2 v1 = *(const float2*)(eb + (r0 + 8) * DE + c0);
                const float2 v2 = *(const float2*)(eb + r0 * DE + c0 + 8);
                const float2 v3 = *(const float2*)(eb + (r0 + 8) * DE + c0 + 8);
                split2h(v0, afr[mblk][ks][0][0], afr[mblk][ks][1][0]);
                split2h(v1, afr[mblk][ks][0][1], afr[mblk][ks][1][1]);
                split2h(v2, afr[mblk][ks][0][2], afr[mblk][ks][1][2]);
                split2h(v3, afr[mblk][ks][0][3], afr[mblk][ks][1][3]);
            }
        }
    }

    // ---- mask products + Q row ----
    sAmv[t] = mask[b * NN + i] * mask[b * NN + t];
    if (t < HD) sQrow[t] = g_Q[(size_t)bi * HD + t];
    __syncthreads();

    // ---- QK scores (fp32 exact): thread t owns j = t ----
    {
        const float4* __restrict__ Kp = (const float4*)(g_K + ((size_t)b * NN + t) * HD);
        #pragma unroll
        for (int hh = 0; hh < NH; hh++) {
            float s_ = 0.f;
            #pragma unroll
            for (int kk = 0; kk < DK / 4; kk++) {
                const float4 kv = Kp[hh * (DK / 4) + kk];
                const float* qp = &sQrow[hh * DK + kk * 4];
                s_ += kv.x * qp[0] + kv.y * qp[1] + kv.z * qp[2] + kv.w * qp[3];
            }
            sQKv[t * 9 + hh] = s_;
        }
    }
    __syncthreads();

    float am4[2][2];
    int   jrow[2][2];
    #pragma unroll
    for (int mblk = 0; mblk < 2; mblk++) {
        #pragma unroll
        for (int uh = 0; uh < 2; uh++) {
            jrow[mblk][uh] = wid * 32 + mblk * 16 + gid + uh * 8;
            am4[mblk][uh]  = sAmv[jrow[mblk][uh]];
        }
    }

    // ldmatrix lane roles: sel 0/1 -> score cols (k0-7 / k8-15), sel 2/3 -> E cols
    const int sel = lid >> 3;
    const int r8  = lid & 7;
    const int nsel = (sel >= 2) ? 128 : 0;
    const uint32_t koff16 = (sel & 1) * 16;
    const float* __restrict__ Vb = g_V + (size_t)b * NN * HD;

    // ---- main loop: 16 col-groups, no block barriers ----
    for (int h0 = 0; h0 < HD; h0 += 64) {
        #pragma unroll 1
        for (int cg = 0; cg < 8; cg++) {
            float accS[2][4] = {{0.f,0.f,0.f,0.f},{0.f,0.f,0.f,0.f}};
            float accE[2][4] = {{0.f,0.f,0.f,0.f},{0.f,0.f,0.f,0.f}};
            const int nrow = h0 + cg * 8 + r8 + nsel;
            const uint32_t rowbase = sbase + SM_B + (uint32_t)nrow * 128;
            const uint32_t xkey = ((uint32_t)nrow & 7) << 4;
            #pragma unroll
            for (int ks = 0; ks < 4; ks++) {
                const uint32_t addr = rowbase + (((uint32_t)ks * 32 + koff16) ^ xkey);
                uint32_t bh[4];
                ldmat_x4(bh, addr);
                #pragma unroll
                for (int mblk = 0; mblk < 2; mblk++) {
                    mma16816(accS[mblk], afr[mblk][ks][0], bh + 0);  // e_hi @ W_hi
                    mma16816(accS[mblk], afr[mblk][ks][1], bh + 0);  // e_lo @ W_hi
                    mma16816(accE[mblk], afr[mblk][ks][0], bh + 2);
                    mma16816(accE[mblk], afr[mblk][ks][1], bh + 2);
                }
            }
            // fragment epilogue: head constant within cg; float2 V loads
            const int head = (h0 + cg * 8) >> 4;
            const int cbase = h0 + cg * 8 + tig * 2;
            float den0 = 0.f, den1 = 0.f, out0 = 0.f, out1 = 0.f;
            #pragma unroll
            for (int mblk = 0; mblk < 2; mblk++) {
                #pragma unroll
                for (int uh = 0; uh < 2; uh++) {
                    const int j  = jrow[mblk][uh];
                    const float qk = sQKv[j * 9 + head];
                    const float am = am4[mblk][uh];
                    const float2 vv = *(const float2*)&Vb[(size_t)j * HD + cbase];

                    float s0 = qk + accS[mblk][uh * 2];
                    s0 = fminf(5.f, fmaxf(-5.f, s0));
                    const float p0 = __expf(s0) * am;
                    den0 += p0;
                    out0 += p0 * am * (vv.x + accE[mblk][uh * 2]);

                    float s1 = qk + accS[mblk][uh * 2 + 1];
                    s1 = fminf(5.f, fmaxf(-5.f, s1));
                    const float p1 = __expf(s1) * am;
                    den1 += p1;
                    out1 += p1 * am * (vv.y + accE[mblk][uh * 2 + 1]);
                }
            }
            #pragma unroll
            for (int m_ = 4; m_ <= 16; m_ <<= 1) {
                den0 += __shfl_xor_sync(0xffffffffu, den0, m_);
                den1 += __shfl_xor_sync(0xffffffffu, den1, m_);
                out0 += __shfl_xor_sync(0xffffffffu, out0, m_);
                out1 += __shfl_xor_sync(0xffffffffu, out1, m_);
            }
            if (gid == 0) {
                *(float2*)&sWden[wid * 128 + cbase] = make_float2(den0, den1);
                *(float2*)&sWout[wid * 128 + cbase] = make_float2(out0, out1);
            }
        }
    }
    __syncthreads();

    // ---- final cross-warp combine ----
    if (t < HD) {
        float D_ = 0.f, O_ = 0.f;
        #pragma unroll
        for (int w = 0; w < 8; w++) {
            D_ += sWden[w * 128 + t];
            O_ += sWout[w * 128 + t];
        }
        out[(size_t)bi * HD + t] = O_ / fmaxf(D_, 1e-6f);
    }
}

// ---------------------------------------------------------------------------
// Launch
// ---------------------------------------------------------------------------
extern "C" void kernel_launch(void* const* d_in, const int* in_sizes, int n_in,
                              void* d_out, int out_size)
{
    const float* h    = (const float*)d_in[0];
    const float* e    = (const float*)d_in[1];
    const float* mask = (const float*)d_in[2];
    const float* WQ   = (const float*)d_in[3];
    const float* WK   = (const float*)d_in[4];
    const float* WV   = (const float*)d_in[5];
    const float* WE   = (const float*)d_in[6];
    const float* WE2  = (const float*)d_in[7];
    float* out = (float*)d_out;

    cudaFuncSetAttribute(attn_mma_kernel,
                         cudaFuncAttributeMaxDynamicSharedMemorySize, SMEM_TOTAL);

    prep_kernel<<<QKV_BLOCKS + 64, 256>>>(h, WQ, WK, WV, WE, WE2);
    attn_mma_kernel<<<BB * NN, 256, SMEM_TOTAL>>>(e, mask, out);
}